// round 7
// baseline (speedup 1.0000x reference)
#include <cuda_runtime.h>
#include <cuda_bf16.h>

#define N_NODES 50000
#define N_EDGES 800000
#define IN_FT   256
#define OUT_FT  128

// ---------------- scratch (device globals; no allocation allowed) ----------
__device__ float g_fts[(size_t)N_NODES * OUT_FT];   // seq_fts [N,128]
__device__ int   g_counts[N_NODES];                 // in-degree per dst
__device__ int   g_cursor[N_NODES];                 // fill cursors
__device__ int   g_offsets[N_NODES];                // exclusive prefix of counts
__device__ int   g_bsums[256];                      // block partial sums for scan
__device__ int2  g_csr[N_EDGES];                    // packed (src, val bits)

// ---------------------------------------------------------------------------
// GEMM: fts[n][o] = sum_k seq[n][k] * W[o][k]
// BM=32 x BN=128 x BK=16, 128 threads, 4x8 per thread via fma.rn.f32x2.
// Smaller BM reduces wave-quantization tail (1563 tiles, occ ~6-7).
// B duplicated in smem, interleaved so inner-loop LDS.128 are conflict-free.
// ---------------------------------------------------------------------------
#define GBM 32
#define GBN 128
#define GBK 16

#define FMA_F32X2(d, a, b) \
    asm("fma.rn.f32x2 %0, %1, %2, %0;" : "+l"(d) : "l"(a), "l"(b))

__global__ __launch_bounds__(128, 6) void gemm_kernel(
    const float* __restrict__ seq,   // [N_NODES, 256]
    const float* __restrict__ W,     // [128, 256]
    float* __restrict__ fts)         // [N_NODES, 128]
{
    __shared__ __align__(16) float As [GBK][GBM + 4];      // 16 x 36
    __shared__ __align__(16) float Bsd[GBK][2 * GBN + 8];  // 16 x 264

    const int tid     = threadIdx.x;
    const int block_m = blockIdx.x * GBM;
    const int tx      = tid & 15;   // cols 8*tx .. 8*tx+7
    const int ty      = tid >> 4;   // rows 4*ty .. 4*ty+3

    unsigned long long acc[2][8];   // acc[p][j]: packed rows (4ty+2p, 4ty+2p+1), col j
#pragma unroll
    for (int p = 0; p < 2; p++)
#pragma unroll
        for (int j = 0; j < 8; j++) acc[p][j] = 0ull;

    for (int k0 = 0; k0 < IN_FT; k0 += GBK) {
        // --- A tile: 32 rows x 16 k = 128 float4, 1 per thread ---
        {
            int row = tid >> 2;          // 0..31
            int kq  = tid & 3;           // float4 along k
            int g_row = block_m + row;
            float4 v = make_float4(0.f, 0.f, 0.f, 0.f);
            if (g_row < N_NODES)
                v = *reinterpret_cast<const float4*>(&seq[(size_t)g_row * IN_FT + k0 + kq * 4]);
            As[kq * 4 + 0][row] = v.x;
            As[kq * 4 + 1][row] = v.y;
            As[kq * 4 + 2][row] = v.z;
            As[kq * 4 + 3][row] = v.w;
        }
        // --- B tile duplicated+interleaved: 128 o x 16 k, 4 float4 per thread
#pragma unroll
        for (int t = 0; t < 4; t++) {
            int idx = tid + t * 128;
            int o  = idx >> 2;           // 0..127
            int kq = idx & 3;
            float4 v = *reinterpret_cast<const float4*>(&W[(size_t)o * IN_FT + k0 + kq * 4]);
            int c    = o >> 1;                       // column pair 0..63
            int half = o & 1;
            int fo   = ((c & 3) * 16 + (c >> 2)) * 4 + half * 2;
            *reinterpret_cast<float2*>(&Bsd[kq * 4 + 0][fo]) = make_float2(v.x, v.x);
            *reinterpret_cast<float2*>(&Bsd[kq * 4 + 1][fo]) = make_float2(v.y, v.y);
            *reinterpret_cast<float2*>(&Bsd[kq * 4 + 2][fo]) = make_float2(v.z, v.z);
            *reinterpret_cast<float2*>(&Bsd[kq * 4 + 3][fo]) = make_float2(v.w, v.w);
        }
        __syncthreads();

#pragma unroll
        for (int k = 0; k < GBK; k++) {
            // A: rows 4ty..4ty+3 -> one LDS.128 (2 packed pairs), broadcast
            ulonglong2 aa = *reinterpret_cast<const ulonglong2*>(&As[k][ty * 4]);
            unsigned long long a0 = aa.x, a1 = aa.y;

            // B: 4 conflict-free LDS.128, each = 2 packed column operands
            unsigned long long b[8];
#pragma unroll
            for (int q = 0; q < 4; q++) {
                ulonglong2 bb = *reinterpret_cast<const ulonglong2*>(
                    &Bsd[k][(q * 16 + tx) * 4]);
                b[2 * q]     = bb.x;
                b[2 * q + 1] = bb.y;
            }

#pragma unroll
            for (int j = 0; j < 8; j++) {
                FMA_F32X2(acc[0][j], a0, b[j]);
                FMA_F32X2(acc[1][j], a1, b[j]);
            }
        }
        __syncthreads();
    }

    // --- store: unpack packed row pairs ---
#pragma unroll
    for (int p = 0; p < 2; p++) {
        float lo[8], hi[8];
#pragma unroll
        for (int j = 0; j < 8; j++) {
            lo[j] = __uint_as_float((unsigned)(acc[p][j]));
            hi[j] = __uint_as_float((unsigned)(acc[p][j] >> 32));
        }
        int r0 = block_m + ty * 4 + 2 * p;
        if (r0 < N_NODES) {
            float* dst = &fts[(size_t)r0 * OUT_FT + tx * 8];
            *reinterpret_cast<float4*>(dst)     = make_float4(lo[0], lo[1], lo[2], lo[3]);
            *reinterpret_cast<float4*>(dst + 4) = make_float4(lo[4], lo[5], lo[6], lo[7]);
        }
        if (r0 + 1 < N_NODES) {
            float* dst = &fts[(size_t)(r0 + 1) * OUT_FT + tx * 8];
            *reinterpret_cast<float4*>(dst)     = make_float4(hi[0], hi[1], hi[2], hi[3]);
            *reinterpret_cast<float4*>(dst + 4) = make_float4(hi[4], hi[5], hi[6], hi[7]);
        }
    }
}

// ---------------------------------------------------------------------------
// CSR build: histogram -> 3-kernel exclusive scan -> fill (packed entries)
// ---------------------------------------------------------------------------
#define SCAN_B 256
#define NUM_SBLK ((N_NODES + SCAN_B - 1) / SCAN_B)   // 196

__global__ void hist_kernel(const int* __restrict__ edge_dst) {
    for (int e = blockIdx.x * blockDim.x + threadIdx.x; e < N_EDGES;
         e += gridDim.x * blockDim.x)
        atomicAdd(&g_counts[edge_dst[e]], 1);
}

__global__ void scan1_kernel() {
    __shared__ int sh[SCAN_B];
    int t = threadIdx.x;
    int i = blockIdx.x * SCAN_B + t;
    int x = (i < N_NODES) ? g_counts[i] : 0;
    sh[t] = x;
    __syncthreads();
#pragma unroll
    for (int off = 1; off < SCAN_B; off <<= 1) {
        int y = (t >= off) ? sh[t - off] : 0;
        __syncthreads();
        sh[t] += y;
        __syncthreads();
    }
    if (i < N_NODES) g_offsets[i] = sh[t] - x;
    if (t == SCAN_B - 1) g_bsums[blockIdx.x] = sh[t];
}

__global__ void scan2_kernel() {
    __shared__ int sh[SCAN_B];
    int t = threadIdx.x;
    int x = (t < NUM_SBLK) ? g_bsums[t] : 0;
    sh[t] = x;
    __syncthreads();
#pragma unroll
    for (int off = 1; off < SCAN_B; off <<= 1) {
        int y = (t >= off) ? sh[t - off] : 0;
        __syncthreads();
        sh[t] += y;
        __syncthreads();
    }
    if (t < NUM_SBLK) g_bsums[t] = sh[t] - x;
}

__global__ void scan3_kernel() {
    int i = blockIdx.x * SCAN_B + threadIdx.x;
    if (i < N_NODES) g_offsets[i] += g_bsums[blockIdx.x];
}

__global__ void fill_kernel(const int* __restrict__ edge_src,
                            const int* __restrict__ edge_dst,
                            const float* __restrict__ edge_val) {
    for (int e = blockIdx.x * blockDim.x + threadIdx.x; e < N_EDGES;
         e += gridDim.x * blockDim.x) {
        int d = edge_dst[e];
        int p = atomicAdd(&g_cursor[d], 1);
        int idx = g_offsets[d] + p;
        g_csr[idx] = make_int2(edge_src[e], __float_as_int(edge_val[e]));
    }
}

// ---------------------------------------------------------------------------
// Gather: one warp per dst node, 8-edge unrolled (loads batched before FMAs
// for high MLP). out[n] = prelu(sum_e val*fts[src] + bias)
// ---------------------------------------------------------------------------
__global__ __launch_bounds__(256) void gather_kernel(
    const float* __restrict__ fts,
    const float* __restrict__ bias,
    const float* __restrict__ prelu_a,
    float*       __restrict__ out)
{
    int warp = (blockIdx.x * blockDim.x + threadIdx.x) >> 5;
    int lane = threadIdx.x & 31;
    if (warp >= N_NODES) return;

    int off = g_offsets[warp];
    int deg = g_counts[warp];

    float4 acc = make_float4(0.f, 0.f, 0.f, 0.f);
    int i = 0;

    for (; i + 8 <= deg; i += 8) {
        int2 e[8];
#pragma unroll
        for (int u = 0; u < 8; u++) e[u] = g_csr[off + i + u];
        float4 m[8];
#pragma unroll
        for (int u = 0; u < 8; u++)
            m[u] = *reinterpret_cast<const float4*>(&fts[(size_t)e[u].x * OUT_FT + lane * 4]);
#pragma unroll
        for (int u = 0; u < 8; u++) {
            float v = __int_as_float(e[u].y);
            acc.x += v * m[u].x;
            acc.y += v * m[u].y;
            acc.z += v * m[u].z;
            acc.w += v * m[u].w;
        }
    }
    for (; i + 2 <= deg; i += 2) {
        int2 e0 = g_csr[off + i];
        int2 e1 = g_csr[off + i + 1];
        float4 m0 = *reinterpret_cast<const float4*>(&fts[(size_t)e0.x * OUT_FT + lane * 4]);
        float4 m1 = *reinterpret_cast<const float4*>(&fts[(size_t)e1.x * OUT_FT + lane * 4]);
        float v0 = __int_as_float(e0.y), v1 = __int_as_float(e1.y);
        acc.x += v0 * m0.x + v1 * m1.x;
        acc.y += v0 * m0.y + v1 * m1.y;
        acc.z += v0 * m0.z + v1 * m1.z;
        acc.w += v0 * m0.w + v1 * m1.w;
    }
    if (i < deg) {
        int2 e = g_csr[off + i];
        float v = __int_as_float(e.y);
        float4 m = *reinterpret_cast<const float4*>(&fts[(size_t)e.x * OUT_FT + lane * 4]);
        acc.x += v * m.x; acc.y += v * m.y; acc.z += v * m.z; acc.w += v * m.w;
    }

    float4 b = *reinterpret_cast<const float4*>(&bias[lane * 4]);
    const float a = prelu_a[0];
    acc.x += b.x; acc.y += b.y; acc.z += b.z; acc.w += b.w;
    acc.x = acc.x >= 0.f ? acc.x : a * acc.x;
    acc.y = acc.y >= 0.f ? acc.y : a * acc.y;
    acc.z = acc.z >= 0.f ? acc.z : a * acc.z;
    acc.w = acc.w >= 0.f ? acc.w : a * acc.w;
    *reinterpret_cast<float4*>(&out[(size_t)warp * OUT_FT + lane * 4]) = acc;
}

// ---------------------------------------------------------------------------
// kernel_launch: GEMM on main stream || CSR build on side stream, join, gather.
// Inputs: seq, edge_src(i32), edge_dst(i32), edge_val, W, bias, prelu_a
// ---------------------------------------------------------------------------
extern "C" void kernel_launch(void* const* d_in, const int* in_sizes, int n_in,
                              void* d_out, int out_size)
{
    const float* seq      = (const float*)d_in[0];
    const int*   edge_src = (const int*)d_in[1];
    const int*   edge_dst = (const int*)d_in[2];
    const float* edge_val = (const float*)d_in[3];
    const float* W        = (const float*)d_in[4];
    const float* bias     = (const float*)d_in[5];
    const float* prelu_a  = (const float*)d_in[6];
    float*       out      = (float*)d_out;

    float* fts = nullptr;
    void *p_counts = nullptr, *p_cursor = nullptr;
    cudaGetSymbolAddress((void**)&fts, g_fts);
    cudaGetSymbolAddress(&p_counts, g_counts);
    cudaGetSymbolAddress(&p_cursor, g_cursor);

    // Lazily-created side stream + events (created once, during the
    // harness's correctness call, i.e. outside graph capture).
    static cudaStream_t s_side = nullptr;
    static cudaEvent_t  ev_fork = nullptr, ev_join = nullptr;
    if (s_side == nullptr) {
        cudaStreamCreateWithFlags(&s_side, cudaStreamNonBlocking);
        cudaEventCreateWithFlags(&ev_fork, cudaEventDisableTiming);
        cudaEventCreateWithFlags(&ev_join, cudaEventDisableTiming);
    }

    // Fork: side stream runs the CSR build concurrently with the GEMM.
    cudaEventRecord(ev_fork, 0);
    cudaStreamWaitEvent(s_side, ev_fork, 0);

    cudaMemsetAsync(p_counts, 0, N_NODES * sizeof(int), s_side);
    cudaMemsetAsync(p_cursor, 0, N_NODES * sizeof(int), s_side);
    hist_kernel<<<3125, 256, 0, s_side>>>(edge_dst);
    scan1_kernel<<<NUM_SBLK, SCAN_B, 0, s_side>>>();
    scan2_kernel<<<1, SCAN_B, 0, s_side>>>();
    scan3_kernel<<<NUM_SBLK, SCAN_B, 0, s_side>>>();
    fill_kernel<<<3125, 256, 0, s_side>>>(edge_src, edge_dst, edge_val);
    cudaEventRecord(ev_join, s_side);

    // Main stream: GEMM (independent of CSR build).
    int gemm_blocks = (N_NODES + GBM - 1) / GBM;   // 1563
    gemm_kernel<<<gemm_blocks, 128>>>(seq, W, fts);

    // Join, then gather + bias + PReLU.
    cudaStreamWaitEvent(0, ev_join, 0);
    int gather_blocks = (N_NODES * 32 + 255) / 256;   // 6250
    gather_kernel<<<gather_blocks, 256>>>(fts, bias, prelu_a, out);
}

// round 8
// speedup vs baseline: 1.5393x; 1.5393x over previous
#include <cuda_runtime.h>
#include <cuda_fp16.h>
#include <cuda_bf16.h>

#define N_NODES 50000
#define N_EDGES 800000
#define IN_FT   256
#define OUT_FT  128

// ---------------- scratch (device globals; no allocation allowed) ----------
__device__ __half g_fts[(size_t)N_NODES * OUT_FT];  // seq_fts [N,128] in fp16
__device__ int    g_counts[N_NODES];                // in-degree per dst
__device__ int    g_cursor[N_NODES];                // fill cursors
__device__ int    g_offsets[N_NODES];               // exclusive prefix of counts
__device__ int    g_bsums[256];                     // block partial sums for scan
__device__ int2   g_csr[N_EDGES];                   // packed (src, val bits)

// ---------------------------------------------------------------------------
// GEMM: fts[n][o] = sum_k seq[n][k] * W[o][k]   (R6 config: BM=64, proven)
// 128 threads, 8x8 per thread via fma.rn.f32x2, fp32 accumulate,
// fp16 store (gather is the only consumer; halves its traffic).
// B duplicated in smem, interleaved so inner-loop LDS.128 are conflict-free.
// ---------------------------------------------------------------------------
#define GBM 64
#define GBN 128
#define GBK 16

#define FMA_F32X2(d, a, b) \
    asm("fma.rn.f32x2 %0, %1, %2, %0;" : "+l"(d) : "l"(a), "l"(b))

__global__ __launch_bounds__(128, 4) void gemm_kernel(
    const float* __restrict__ seq,   // [N_NODES, 256]
    const float* __restrict__ W,     // [128, 256]
    __half* __restrict__ fts)        // [N_NODES, 128] fp16
{
    __shared__ __align__(16) float As [GBK][GBM + 4];
    __shared__ __align__(16) float Bsd[GBK][2 * GBN + 8];

    const int tid     = threadIdx.x;
    const int block_m = blockIdx.x * GBM;
    const int tx      = tid & 15;   // cols 8*tx .. 8*tx+7
    const int ty      = tid >> 4;   // rows 8*ty .. 8*ty+7

    unsigned long long acc[4][8];   // acc[p][j]: packed rows (2p,2p+1), col j
#pragma unroll
    for (int p = 0; p < 4; p++)
#pragma unroll
        for (int j = 0; j < 8; j++) acc[p][j] = 0ull;

    for (int k0 = 0; k0 < IN_FT; k0 += GBK) {
        // --- A tile: 64 rows x 16 k = 256 float4, 2 per thread ---
#pragma unroll
        for (int t = 0; t < 2; t++) {
            int idx = tid + t * 128;
            int row = idx >> 2;
            int kq  = idx & 3;
            int g_row = block_m + row;
            float4 v = make_float4(0.f, 0.f, 0.f, 0.f);
            if (g_row < N_NODES)
                v = *reinterpret_cast<const float4*>(&seq[(size_t)g_row * IN_FT + k0 + kq * 4]);
            As[kq * 4 + 0][row] = v.x;
            As[kq * 4 + 1][row] = v.y;
            As[kq * 4 + 2][row] = v.z;
            As[kq * 4 + 3][row] = v.w;
        }
        // --- B tile duplicated+interleaved: 128 o x 16 k, 4 float4 per thread
#pragma unroll
        for (int t = 0; t < 4; t++) {
            int idx = tid + t * 128;
            int o  = idx >> 2;
            int kq = idx & 3;
            float4 v = *reinterpret_cast<const float4*>(&W[(size_t)o * IN_FT + k0 + kq * 4]);
            int c    = o >> 1;
            int half = o & 1;
            int fo   = ((c & 3) * 16 + (c >> 2)) * 4 + half * 2;
            *reinterpret_cast<float2*>(&Bsd[kq * 4 + 0][fo]) = make_float2(v.x, v.x);
            *reinterpret_cast<float2*>(&Bsd[kq * 4 + 1][fo]) = make_float2(v.y, v.y);
            *reinterpret_cast<float2*>(&Bsd[kq * 4 + 2][fo]) = make_float2(v.z, v.z);
            *reinterpret_cast<float2*>(&Bsd[kq * 4 + 3][fo]) = make_float2(v.w, v.w);
        }
        __syncthreads();

#pragma unroll
        for (int k = 0; k < GBK; k++) {
            const unsigned long long* pa =
                reinterpret_cast<const unsigned long long*>(&As[k][ty * 8]);
            unsigned long long a0 = pa[0], a1 = pa[1], a2 = pa[2], a3 = pa[3];

            unsigned long long b[8];
#pragma unroll
            for (int q = 0; q < 4; q++) {
                ulonglong2 bb = *reinterpret_cast<const ulonglong2*>(
                    &Bsd[k][(q * 16 + tx) * 4]);
                b[2 * q]     = bb.x;
                b[2 * q + 1] = bb.y;
            }

#pragma unroll
            for (int j = 0; j < 8; j++) {
                FMA_F32X2(acc[0][j], a0, b[j]);
                FMA_F32X2(acc[1][j], a1, b[j]);
                FMA_F32X2(acc[2][j], a2, b[j]);
                FMA_F32X2(acc[3][j], a3, b[j]);
            }
        }
        __syncthreads();
    }

    // --- store: unpack packed row pairs, convert to fp16, one 16B store/row ---
#pragma unroll
    for (int p = 0; p < 4; p++) {
        float lo[8], hi[8];
#pragma unroll
        for (int j = 0; j < 8; j++) {
            lo[j] = __uint_as_float((unsigned)(acc[p][j]));
            hi[j] = __uint_as_float((unsigned)(acc[p][j] >> 32));
        }
        int r0 = block_m + ty * 8 + 2 * p;
        if (r0 < N_NODES) {
            __half2 h[4];
#pragma unroll
            for (int q = 0; q < 4; q++) h[q] = __floats2half2_rn(lo[2*q], lo[2*q+1]);
            *reinterpret_cast<uint4*>(&fts[(size_t)r0 * OUT_FT + tx * 8]) =
                *reinterpret_cast<uint4*>(h);
        }
        if (r0 + 1 < N_NODES) {
            __half2 h[4];
#pragma unroll
            for (int q = 0; q < 4; q++) h[q] = __floats2half2_rn(hi[2*q], hi[2*q+1]);
            *reinterpret_cast<uint4*>(&fts[(size_t)(r0 + 1) * OUT_FT + tx * 8]) =
                *reinterpret_cast<uint4*>(h);
        }
    }
}

// ---------------------------------------------------------------------------
// CSR build: histogram -> 3-kernel exclusive scan -> fill (packed entries)
// ---------------------------------------------------------------------------
#define SCAN_B 256
#define NUM_SBLK ((N_NODES + SCAN_B - 1) / SCAN_B)   // 196

__global__ void hist_kernel(const int* __restrict__ edge_dst) {
    for (int e = blockIdx.x * blockDim.x + threadIdx.x; e < N_EDGES;
         e += gridDim.x * blockDim.x)
        atomicAdd(&g_counts[edge_dst[e]], 1);
}

__global__ void scan1_kernel() {
    __shared__ int sh[SCAN_B];
    int t = threadIdx.x;
    int i = blockIdx.x * SCAN_B + t;
    int x = (i < N_NODES) ? g_counts[i] : 0;
    sh[t] = x;
    __syncthreads();
#pragma unroll
    for (int off = 1; off < SCAN_B; off <<= 1) {
        int y = (t >= off) ? sh[t - off] : 0;
        __syncthreads();
        sh[t] += y;
        __syncthreads();
    }
    if (i < N_NODES) g_offsets[i] = sh[t] - x;
    if (t == SCAN_B - 1) g_bsums[blockIdx.x] = sh[t];
}

__global__ void scan2_kernel() {
    __shared__ int sh[SCAN_B];
    int t = threadIdx.x;
    int x = (t < NUM_SBLK) ? g_bsums[t] : 0;
    sh[t] = x;
    __syncthreads();
#pragma unroll
    for (int off = 1; off < SCAN_B; off <<= 1) {
        int y = (t >= off) ? sh[t - off] : 0;
        __syncthreads();
        sh[t] += y;
        __syncthreads();
    }
    if (t < NUM_SBLK) g_bsums[t] = sh[t] - x;
}

__global__ void scan3_kernel() {
    int i = blockIdx.x * SCAN_B + threadIdx.x;
    if (i < N_NODES) g_offsets[i] += g_bsums[blockIdx.x];
}

__global__ void fill_kernel(const int* __restrict__ edge_src,
                            const int* __restrict__ edge_dst,
                            const float* __restrict__ edge_val) {
    for (int e = blockIdx.x * blockDim.x + threadIdx.x; e < N_EDGES;
         e += gridDim.x * blockDim.x) {
        int d = edge_dst[e];
        int p = atomicAdd(&g_cursor[d], 1);
        int idx = g_offsets[d] + p;
        g_csr[idx] = make_int2(edge_src[e], __float_as_int(edge_val[e]));
    }
}

// ---------------------------------------------------------------------------
// Gather: one warp per dst node, 8-edge unrolled. fts rows are fp16
// (8B per lane per edge), accumulate fp32.
// out[n] = prelu(sum_e val*fts[src] + bias)
// ---------------------------------------------------------------------------
__device__ __forceinline__ void acc_edge(float4& acc, float v, uint2 raw) {
    __half2 h0 = *reinterpret_cast<__half2*>(&raw.x);
    __half2 h1 = *reinterpret_cast<__half2*>(&raw.y);
    float2 f0 = __half22float2(h0);
    float2 f1 = __half22float2(h1);
    acc.x += v * f0.x;
    acc.y += v * f0.y;
    acc.z += v * f1.x;
    acc.w += v * f1.y;
}

__global__ __launch_bounds__(256) void gather_kernel(
    const __half* __restrict__ fts,
    const float*  __restrict__ bias,
    const float*  __restrict__ prelu_a,
    float*        __restrict__ out)
{
    int warp = (blockIdx.x * blockDim.x + threadIdx.x) >> 5;
    int lane = threadIdx.x & 31;
    if (warp >= N_NODES) return;

    int off = g_offsets[warp];
    int deg = g_counts[warp];

    float4 acc = make_float4(0.f, 0.f, 0.f, 0.f);
    int i = 0;

    for (; i + 8 <= deg; i += 8) {
        int2 e[8];
#pragma unroll
        for (int u = 0; u < 8; u++) e[u] = g_csr[off + i + u];
        uint2 m[8];
#pragma unroll
        for (int u = 0; u < 8; u++)
            m[u] = *reinterpret_cast<const uint2*>(&fts[(size_t)e[u].x * OUT_FT + lane * 4]);
#pragma unroll
        for (int u = 0; u < 8; u++)
            acc_edge(acc, __int_as_float(e[u].y), m[u]);
    }
    for (; i + 2 <= deg; i += 2) {
        int2 e0 = g_csr[off + i];
        int2 e1 = g_csr[off + i + 1];
        uint2 m0 = *reinterpret_cast<const uint2*>(&fts[(size_t)e0.x * OUT_FT + lane * 4]);
        uint2 m1 = *reinterpret_cast<const uint2*>(&fts[(size_t)e1.x * OUT_FT + lane * 4]);
        acc_edge(acc, __int_as_float(e0.y), m0);
        acc_edge(acc, __int_as_float(e1.y), m1);
    }
    if (i < deg) {
        int2 e = g_csr[off + i];
        uint2 m = *reinterpret_cast<const uint2*>(&fts[(size_t)e.x * OUT_FT + lane * 4]);
        acc_edge(acc, __int_as_float(e.y), m);
    }

    float4 b = *reinterpret_cast<const float4*>(&bias[lane * 4]);
    const float a = prelu_a[0];
    acc.x += b.x; acc.y += b.y; acc.z += b.z; acc.w += b.w;
    acc.x = acc.x >= 0.f ? acc.x : a * acc.x;
    acc.y = acc.y >= 0.f ? acc.y : a * acc.y;
    acc.z = acc.z >= 0.f ? acc.z : a * acc.z;
    acc.w = acc.w >= 0.f ? acc.w : a * acc.w;
    *reinterpret_cast<float4*>(&out[(size_t)warp * OUT_FT + lane * 4]) = acc;
}

// ---------------------------------------------------------------------------
// kernel_launch: GEMM on main stream || CSR build on side stream, join, gather.
// Inputs: seq, edge_src(i32), edge_dst(i32), edge_val, W, bias, prelu_a
// ---------------------------------------------------------------------------
extern "C" void kernel_launch(void* const* d_in, const int* in_sizes, int n_in,
                              void* d_out, int out_size)
{
    const float* seq      = (const float*)d_in[0];
    const int*   edge_src = (const int*)d_in[1];
    const int*   edge_dst = (const int*)d_in[2];
    const float* edge_val = (const float*)d_in[3];
    const float* W        = (const float*)d_in[4];
    const float* bias     = (const float*)d_in[5];
    const float* prelu_a  = (const float*)d_in[6];
    float*       out      = (float*)d_out;

    __half* fts = nullptr;
    void *p_counts = nullptr, *p_cursor = nullptr;
    cudaGetSymbolAddress((void**)&fts, g_fts);
    cudaGetSymbolAddress(&p_counts, g_counts);
    cudaGetSymbolAddress(&p_cursor, g_cursor);

    // Lazily-created side stream + events (created once, during the
    // harness's correctness call, i.e. outside graph capture).
    static cudaStream_t s_side = nullptr;
    static cudaEvent_t  ev_fork = nullptr, ev_join = nullptr;
    if (s_side == nullptr) {
        cudaStreamCreateWithFlags(&s_side, cudaStreamNonBlocking);
        cudaEventCreateWithFlags(&ev_fork, cudaEventDisableTiming);
        cudaEventCreateWithFlags(&ev_join, cudaEventDisableTiming);
    }

    // Fork: side stream runs the CSR build concurrently with the GEMM.
    cudaEventRecord(ev_fork, 0);
    cudaStreamWaitEvent(s_side, ev_fork, 0);

    cudaMemsetAsync(p_counts, 0, N_NODES * sizeof(int), s_side);
    cudaMemsetAsync(p_cursor, 0, N_NODES * sizeof(int), s_side);
    hist_kernel<<<3125, 256, 0, s_side>>>(edge_dst);
    scan1_kernel<<<NUM_SBLK, SCAN_B, 0, s_side>>>();
    scan2_kernel<<<1, SCAN_B, 0, s_side>>>();
    scan3_kernel<<<NUM_SBLK, SCAN_B, 0, s_side>>>();
    fill_kernel<<<3125, 256, 0, s_side>>>(edge_src, edge_dst, edge_val);
    cudaEventRecord(ev_join, s_side);

    // Main stream: GEMM (independent of CSR build).
    int gemm_blocks = (N_NODES + GBM - 1) / GBM;   // 782
    gemm_kernel<<<gemm_blocks, 128>>>(seq, W, fts);

    // Join, then gather + bias + PReLU.
    cudaStreamWaitEvent(0, ev_join, 0);
    int gather_blocks = (N_NODES * 32 + 255) / 256;   // 6250
    gather_kernel<<<gather_blocks, 256>>>(fts, bias, prelu_a, out);
}

// round 9
// speedup vs baseline: 2.0437x; 1.3277x over previous
#include <cuda_runtime.h>
#include <cuda_fp16.h>
#include <cuda_bf16.h>

#define N_NODES 50000
#define N_EDGES 800000
#define IN_FT   256
#define OUT_FT  128

// ---------------- scratch (device globals; no allocation allowed) ----------
__device__ __half g_fts[(size_t)N_NODES * OUT_FT];  // seq_fts [N,128] in fp16
__device__ int    g_counts[N_NODES];                // in-degree per dst
__device__ int    g_cursor[N_NODES];                // fill cursors
__device__ int    g_offsets[N_NODES];               // exclusive prefix of counts
__device__ int    g_bsums[256];                     // block partial sums for scan
__device__ int2   g_csr[N_EDGES];                   // packed (src, val bits)

// ---------------------------------------------------------------------------
// GEMM: fts[n][o] = sum_k seq[n][k] * W[o][k]
// BM=64 x BN=128 x BK=16, 128 threads, 8x8 per thread via fma.rn.f32x2.
// NO smem duplication: A natural (32B/thr/k) + B natural packed (32B/thr/k);
// duplicated (a_i,a_i) operands built in registers (ALU pipe, idle).
// B stored quad-permuted: quad j at 16B-slot (j&1)*16+(j>>1) -> both
// per-thread LDS.128 conflict-free. Crossbar 384->256 cyc/SM/k-step.
// ---------------------------------------------------------------------------
#define GBM 64
#define GBN 128
#define GBK 16

#define FMA_F32X2(d, a, b) \
    asm("fma.rn.f32x2 %0, %1, %2, %0;" : "+l"(d) : "l"(a), "l"(b))
#define PACK_DUP(d, s) \
    asm("mov.b64 %0, {%1, %1};" : "=l"(d) : "f"(s))

__global__ __launch_bounds__(128, 4) void gemm_kernel(
    const float* __restrict__ seq,   // [N_NODES, 256]
    const float* __restrict__ W,     // [128, 256]
    __half* __restrict__ fts)        // [N_NODES, 128] fp16
{
    __shared__ __align__(16) float As[GBK][GBM + 4];    // 16 x 68
    __shared__ __align__(16) float Bs[GBK][GBN + 8];    // 16 x 136 (permuted quads)

    const int tid     = threadIdx.x;
    const int block_m = blockIdx.x * GBM;
    const int tx      = tid & 15;   // cols 8*tx .. 8*tx+7
    const int ty      = tid >> 4;   // rows 8*ty .. 8*ty+7

    unsigned long long acc[8][4];   // acc[i][q]: packed cols (8tx+2q, 8tx+2q+1) of row i
#pragma unroll
    for (int i = 0; i < 8; i++)
#pragma unroll
        for (int q = 0; q < 4; q++) acc[i][q] = 0ull;

    for (int k0 = 0; k0 < IN_FT; k0 += GBK) {
        // --- A tile: 64 rows x 16 k = 256 float4, 2 per thread ---
#pragma unroll
        for (int t = 0; t < 2; t++) {
            int idx = tid + t * 128;
            int row = idx >> 2;
            int kq  = idx & 3;
            int g_row = block_m + row;
            float4 v = make_float4(0.f, 0.f, 0.f, 0.f);
            if (g_row < N_NODES)
                v = *reinterpret_cast<const float4*>(&seq[(size_t)g_row * IN_FT + k0 + kq * 4]);
            As[kq * 4 + 0][row] = v.x;
            As[kq * 4 + 1][row] = v.y;
            As[kq * 4 + 2][row] = v.z;
            As[kq * 4 + 3][row] = v.w;
        }
        // --- B tile, quad-permuted, NOT duplicated: 128 o x 16 k ---
        // col o -> quad j=o>>2, pos=o&3; quad j at 16B-slot (j&1)*16+(j>>1)
#pragma unroll
        for (int t = 0; t < 4; t++) {
            int idx = tid + t * 128;
            int o  = idx >> 2;           // 0..127
            int kq = idx & 3;
            float4 v = *reinterpret_cast<const float4*>(&W[(size_t)o * IN_FT + k0 + kq * 4]);
            int j    = o >> 2;
            int pos  = o & 3;
            int fo   = ((j & 1) * 16 + (j >> 1)) * 4 + pos;
            Bs[kq * 4 + 0][fo] = v.x;
            Bs[kq * 4 + 1][fo] = v.y;
            Bs[kq * 4 + 2][fo] = v.z;
            Bs[kq * 4 + 3][fo] = v.w;
        }
        __syncthreads();

#pragma unroll
        for (int k = 0; k < GBK; k++) {
            // A: 8 rows, 2 broadcast LDS.128, then duplicate into packed pairs
            float4 av0 = *reinterpret_cast<const float4*>(&As[k][ty * 8]);
            float4 av1 = *reinterpret_cast<const float4*>(&As[k][ty * 8 + 4]);
            float a[8] = {av0.x, av0.y, av0.z, av0.w, av1.x, av1.y, av1.z, av1.w};
            unsigned long long ad[8];
#pragma unroll
            for (int i = 0; i < 8; i++) PACK_DUP(ad[i], a[i]);

            // B: 2 conflict-free LDS.128 -> 4 natural packed column pairs
            // quad 2tx at slot tx (float 4tx), quad 2tx+1 at slot 16+tx (float 64+4tx)
            ulonglong2 b0 = *reinterpret_cast<const ulonglong2*>(&Bs[k][4 * tx]);
            ulonglong2 b1 = *reinterpret_cast<const ulonglong2*>(&Bs[k][64 + 4 * tx]);
            unsigned long long b[4] = {b0.x, b0.y, b1.x, b1.y};

#pragma unroll
            for (int i = 0; i < 8; i++) {
                FMA_F32X2(acc[i][0], ad[i], b[0]);
                FMA_F32X2(acc[i][1], ad[i], b[1]);
                FMA_F32X2(acc[i][2], ad[i], b[2]);
                FMA_F32X2(acc[i][3], ad[i], b[3]);
            }
        }
        __syncthreads();
    }

    // --- store: each acc[i][q] = (col 8tx+2q, 8tx+2q+1); convert fp16 ---
#pragma unroll
    for (int i = 0; i < 8; i++) {
        int g_row = block_m + ty * 8 + i;
        if (g_row < N_NODES) {
            __half2 h[4];
#pragma unroll
            for (int q = 0; q < 4; q++) {
                float lo = __uint_as_float((unsigned)(acc[i][q]));
                float hi = __uint_as_float((unsigned)(acc[i][q] >> 32));
                h[q] = __floats2half2_rn(lo, hi);
            }
            *reinterpret_cast<uint4*>(&fts[(size_t)g_row * OUT_FT + tx * 8]) =
                *reinterpret_cast<uint4*>(h);
        }
    }
}

// ---------------------------------------------------------------------------
// CSR build: histogram -> 3-kernel exclusive scan -> fill (packed entries)
// ---------------------------------------------------------------------------
#define SCAN_B 256
#define NUM_SBLK ((N_NODES + SCAN_B - 1) / SCAN_B)   // 196

__global__ void hist_kernel(const int* __restrict__ edge_dst) {
    for (int e = blockIdx.x * blockDim.x + threadIdx.x; e < N_EDGES;
         e += gridDim.x * blockDim.x)
        atomicAdd(&g_counts[edge_dst[e]], 1);
}

__global__ void scan1_kernel() {
    __shared__ int sh[SCAN_B];
    int t = threadIdx.x;
    int i = blockIdx.x * SCAN_B + t;
    int x = (i < N_NODES) ? g_counts[i] : 0;
    sh[t] = x;
    __syncthreads();
#pragma unroll
    for (int off = 1; off < SCAN_B; off <<= 1) {
        int y = (t >= off) ? sh[t - off] : 0;
        __syncthreads();
        sh[t] += y;
        __syncthreads();
    }
    if (i < N_NODES) g_offsets[i] = sh[t] - x;
    if (t == SCAN_B - 1) g_bsums[blockIdx.x] = sh[t];
}

__global__ void scan2_kernel() {
    __shared__ int sh[SCAN_B];
    int t = threadIdx.x;
    int x = (t < NUM_SBLK) ? g_bsums[t] : 0;
    sh[t] = x;
    __syncthreads();
#pragma unroll
    for (int off = 1; off < SCAN_B; off <<= 1) {
        int y = (t >= off) ? sh[t - off] : 0;
        __syncthreads();
        sh[t] += y;
        __syncthreads();
    }
    if (t < NUM_SBLK) g_bsums[t] = sh[t] - x;
}

__global__ void scan3_kernel() {
    int i = blockIdx.x * SCAN_B + threadIdx.x;
    if (i < N_NODES) g_offsets[i] += g_bsums[blockIdx.x];
}

__global__ void fill_kernel(const int* __restrict__ edge_src,
                            const int* __restrict__ edge_dst,
                            const float* __restrict__ edge_val) {
    for (int e = blockIdx.x * blockDim.x + threadIdx.x; e < N_EDGES;
         e += gridDim.x * blockDim.x) {
        int d = edge_dst[e];
        int p = atomicAdd(&g_cursor[d], 1);
        int idx = g_offsets[d] + p;
        g_csr[idx] = make_int2(edge_src[e], __float_as_int(edge_val[e]));
    }
}

// ---------------------------------------------------------------------------
// Gather: one warp per dst node, 8-edge unrolled, fp16 fts, fp32 accumulate.
// ---------------------------------------------------------------------------
__device__ __forceinline__ void acc_edge(float4& acc, float v, uint2 raw) {
    __half2 h0 = *reinterpret_cast<__half2*>(&raw.x);
    __half2 h1 = *reinterpret_cast<__half2*>(&raw.y);
    float2 f0 = __half22float2(h0);
    float2 f1 = __half22float2(h1);
    acc.x += v * f0.x;
    acc.y += v * f0.y;
    acc.z += v * f1.x;
    acc.w += v * f1.y;
}

__global__ __launch_bounds__(256) void gather_kernel(
    const __half* __restrict__ fts,
    const float*  __restrict__ bias,
    const float*  __restrict__ prelu_a,
    float*        __restrict__ out)
{
    int warp = (blockIdx.x * blockDim.x + threadIdx.x) >> 5;
    int lane = threadIdx.x & 31;
    if (warp >= N_NODES) return;

    int off = g_offsets[warp];
    int deg = g_counts[warp];

    float4 acc = make_float4(0.f, 0.f, 0.f, 0.f);
    int i = 0;

    for (; i + 8 <= deg; i += 8) {
        int2 e[8];
#pragma unroll
        for (int u = 0; u < 8; u++) e[u] = g_csr[off + i + u];
        uint2 m[8];
#pragma unroll
        for (int u = 0; u < 8; u++)
            m[u] = *reinterpret_cast<const uint2*>(&fts[(size_t)e[u].x * OUT_FT + lane * 4]);
#pragma unroll
        for (int u = 0; u < 8; u++)
            acc_edge(acc, __int_as_float(e[u].y), m[u]);
    }
    for (; i + 2 <= deg; i += 2) {
        int2 e0 = g_csr[off + i];
        int2 e1 = g_csr[off + i + 1];
        uint2 m0 = *reinterpret_cast<const uint2*>(&fts[(size_t)e0.x * OUT_FT + lane * 4]);
        uint2 m1 = *reinterpret_cast<const uint2*>(&fts[(size_t)e1.x * OUT_FT + lane * 4]);
        acc_edge(acc, __int_as_float(e0.y), m0);
        acc_edge(acc, __int_as_float(e1.y), m1);
    }
    if (i < deg) {
        int2 e = g_csr[off + i];
        uint2 m = *reinterpret_cast<const uint2*>(&fts[(size_t)e.x * OUT_FT + lane * 4]);
        acc_edge(acc, __int_as_float(e.y), m);
    }

    float4 b = *reinterpret_cast<const float4*>(&bias[lane * 4]);
    const float a = prelu_a[0];
    acc.x += b.x; acc.y += b.y; acc.z += b.z; acc.w += b.w;
    acc.x = acc.x >= 0.f ? acc.x : a * acc.x;
    acc.y = acc.y >= 0.f ? acc.y : a * acc.y;
    acc.z = acc.z >= 0.f ? acc.z : a * acc.z;
    acc.w = acc.w >= 0.f ? acc.w : a * acc.w;
    *reinterpret_cast<float4*>(&out[(size_t)warp * OUT_FT + lane * 4]) = acc;
}

// ---------------------------------------------------------------------------
// kernel_launch: GEMM on main stream || CSR build on side stream, join, gather.
// Inputs: seq, edge_src(i32), edge_dst(i32), edge_val, W, bias, prelu_a
// ---------------------------------------------------------------------------
extern "C" void kernel_launch(void* const* d_in, const int* in_sizes, int n_in,
                              void* d_out, int out_size)
{
    const float* seq      = (const float*)d_in[0];
    const int*   edge_src = (const int*)d_in[1];
    const int*   edge_dst = (const int*)d_in[2];
    const float* edge_val = (const float*)d_in[3];
    const float* W        = (const float*)d_in[4];
    const float* bias     = (const float*)d_in[5];
    const float* prelu_a  = (const float*)d_in[6];
    float*       out      = (float*)d_out;

    __half* fts = nullptr;
    void *p_counts = nullptr, *p_cursor = nullptr;
    cudaGetSymbolAddress((void**)&fts, g_fts);
    cudaGetSymbolAddress(&p_counts, g_counts);
    cudaGetSymbolAddress(&p_cursor, g_cursor);

    // Lazily-created side stream + events (created once, during the
    // harness's correctness call, i.e. outside graph capture).
    static cudaStream_t s_side = nullptr;
    static cudaEvent_t  ev_fork = nullptr, ev_join = nullptr;
    if (s_side == nullptr) {
        cudaStreamCreateWithFlags(&s_side, cudaStreamNonBlocking);
        cudaEventCreateWithFlags(&ev_fork, cudaEventDisableTiming);
        cudaEventCreateWithFlags(&ev_join, cudaEventDisableTiming);
    }

    // Fork: side stream runs the CSR build concurrently with the GEMM.
    cudaEventRecord(ev_fork, 0);
    cudaStreamWaitEvent(s_side, ev_fork, 0);

    cudaMemsetAsync(p_counts, 0, N_NODES * sizeof(int), s_side);
    cudaMemsetAsync(p_cursor, 0, N_NODES * sizeof(int), s_side);
    hist_kernel<<<3125, 256, 0, s_side>>>(edge_dst);
    scan1_kernel<<<NUM_SBLK, SCAN_B, 0, s_side>>>();
    scan2_kernel<<<1, SCAN_B, 0, s_side>>>();
    scan3_kernel<<<NUM_SBLK, SCAN_B, 0, s_side>>>();
    fill_kernel<<<3125, 256, 0, s_side>>>(edge_src, edge_dst, edge_val);
    cudaEventRecord(ev_join, s_side);

    // Main stream: GEMM (independent of CSR build).
    int gemm_blocks = (N_NODES + GBM - 1) / GBM;   // 782
    gemm_kernel<<<gemm_blocks, 128>>>(seq, W, fts);

    // Join, then gather + bias + PReLU.
    cudaStreamWaitEvent(0, ev_join, 0);
    int gather_blocks = (N_NODES * 32 + 255) / 256;   // 6250
    gather_kernel<<<gather_blocks, 256>>>(fts, bias, prelu_a, out);
}